// round 15
// baseline (speedup 1.0000x reference)
#include <cuda_runtime.h>
#include <cuda_bf16.h>
#include <math.h>
#include <stdint.h>

// Problem constants
#define Bq 4
#define Hh 8
#define Ss 2048
#define Dd 128
#define QKV_ELEMS (Bq*Hh*Ss*Dd)
#define X_ELEMS (Bq*Ss*Dd)
#define W_ELEMS (Hh*Dd*Dd)
#define SCALE 0.0883883476483184406f   // 1/sqrt(128)

__device__ __nv_bfloat16 g_Qhi[QKV_ELEMS];
__device__ __nv_bfloat16 g_Qlo[QKV_ELEMS];
__device__ __nv_bfloat16 g_Khi[QKV_ELEMS];
__device__ __nv_bfloat16 g_Klo[QKV_ELEMS];
__device__ __nv_bfloat16 g_Vhi[QKV_ELEMS];
__device__ __nv_bfloat16 g_Vlo[QKV_ELEMS];

__device__ __nv_bfloat16 g_xhi[X_ELEMS];
__device__ __nv_bfloat16 g_xlo[X_ELEMS];
__device__ __nv_bfloat16 g_Whi[3 * W_ELEMS];
__device__ __nv_bfloat16 g_Wlo[3 * W_ELEMS];

#define GRID 296
#define SPLIT_UNITS 296
#define PROJ_UNITS 384
#define ATTN_UNITS 1024
#define TOTAL_UNITS (SPLIT_UNITS + PROJ_UNITS + ATTN_UNITS)   // 1704
#define PROJ_BASE SPLIT_UNITS
#define ATTN_BASE (SPLIT_UNITS + PROJ_UNITS)

// Persistent-kernel state. Statically initialized for the FIRST launch;
// the last CTA to exit resets everything so graph replays see fresh state.
__device__ int g_ctr = GRID;
__device__ int g_split = 0;
__device__ int g_done[Hh] = {0, 0, 0, 0, 0, 0, 0, 0};
__device__ int g_fin = 0;

// ===========================================================================
// Common helpers
// ===========================================================================
__device__ __forceinline__ uint32_t swz(uint32_t o) {
    return o ^ (((o >> 8) & 7) << 4);
}
__device__ __forceinline__ uint32_t pk(float e_lo, float e_hi) {
    uint32_t r;
    asm("cvt.rn.bf16x2.f32 %0, %1, %2;" : "=r"(r) : "f"(e_hi), "f"(e_lo));
    return r;
}
__device__ __forceinline__ void sp(float x, float& hf, float& lf) {
    __nv_bfloat16 hb = __float2bfloat16(x);
    hf = __bfloat162float(hb);
    lf = x - hf;
}
__device__ __forceinline__ void ldsm4(uint32_t addr, uint32_t r[4]) {
    asm volatile("ldmatrix.sync.aligned.m8n8.x4.shared.b16 {%0,%1,%2,%3}, [%4];"
                 : "=r"(r[0]), "=r"(r[1]), "=r"(r[2]), "=r"(r[3]) : "r"(addr));
}
__device__ __forceinline__ void ldsm4t(uint32_t addr, uint32_t r[4]) {
    asm volatile("ldmatrix.sync.aligned.m8n8.x4.trans.shared.b16 {%0,%1,%2,%3}, [%4];"
                 : "=r"(r[0]), "=r"(r[1]), "=r"(r[2]), "=r"(r[3]) : "r"(addr));
}
__device__ __forceinline__ void mma16816(float c[4], const uint32_t a[4],
                                         uint32_t b0, uint32_t b1) {
    asm volatile(
        "mma.sync.aligned.m16n8k16.row.col.f32.bf16.bf16.f32 "
        "{%0,%1,%2,%3}, {%4,%5,%6,%7}, {%8,%9}, {%0,%1,%2,%3};"
        : "+f"(c[0]), "+f"(c[1]), "+f"(c[2]), "+f"(c[3])
        : "r"(a[0]), "r"(a[1]), "r"(a[2]), "r"(a[3]), "r"(b0), "r"(b1));
}
__device__ __forceinline__ void cpa(uint32_t dst, const void* src) {
    asm volatile("cp.async.cg.shared.global [%0], [%1], 16;" :: "r"(dst), "l"(src));
}
#define CP_COMMIT()  asm volatile("cp.async.commit_group;" ::: "memory")
#define CP_WAIT(n)   asm volatile("cp.async.wait_group %0;" :: "n"(n) : "memory")

// Split partitioning
#define X4 (X_ELEMS / 4)          // 262144
#define W4 (W_ELEMS / 4)          // 32768
#define TOT4 (X4 + 3 * W4)        // 360448
#define SPLIT_CHUNK ((TOT4 + SPLIT_UNITS - 1) / SPLIT_UNITS)   // 1218

// smem layouts (disjoint in time, same allocation):
//  proj: W hi/lo 0..64KB, x slices 64..96KB (2 x 16KB)
//  attn: Q hi/lo 0..32KB, KV buffers 32..96KB (2 x 32KB)
#define PWHI 0
#define PWLO 32768
#define PXS0 65536
#define PXSTR 16384

#define QHI 0
#define QLO 16384
#define BUF0 32768
#define BUFSTRIDE 32768
#define BKHI 0
#define BKLO 8192
#define BVHI 16384
#define BVLO 24576

#define UNIT_SLOT 98304
#define FUSED_SMEM 98432

__device__ __forceinline__ void prefetch_kv32(uint32_t sb, int buf,
                                              const __nv_bfloat16* Kh, const __nv_bfloat16* Kl,
                                              const __nv_bfloat16* Vh, const __nv_bfloat16* Vl,
                                              int kt, int tid) {
    uint32_t base = sb + BUF0 + buf * BUFSTRIDE;
    size_t goff = (size_t)kt * 32 * 128;
#pragma unroll
    for (int it = 0; it < 4; it++) {
        int idx = tid + it * 128;
        int r = idx >> 4, s = idx & 15;
        uint32_t o = swz((uint32_t)(r * 256 + s * 16));
        size_t ge = goff + (size_t)r * 128 + s * 8;
        cpa(base + BKHI + o, Kh + ge);
        cpa(base + BKLO + o, Kl + ge);
        cpa(base + BVHI + o, Vh + ge);
        cpa(base + BVLO + o, Vl + ge);
    }
}

__global__ __launch_bounds__(128, 2)
void fused_mma(float* __restrict__ out,
               const float* __restrict__ xin,
               const float* __restrict__ wq,
               const float* __restrict__ wk,
               const float* __restrict__ wv)
{
    extern __shared__ char sm[];
    const uint32_t sb = (uint32_t)__cvta_generic_to_shared(sm);
    volatile int* unit_sh = reinterpret_cast<volatile int*>(sm + UNIT_SLOT);
    const int tid  = threadIdx.x;
    const int wid  = tid >> 5;
    const int lane = tid & 31;

    const int l15 = lane & 15;
    const int lhi8 = (lane >> 4) << 3;
    const int bl_row = ((lane >> 4) << 3) + (lane & 7);
    const int bl_col = ((lane >> 3) & 1) << 3;
    const int g = lane >> 2;
    const int t = lane & 3;

    int unit = blockIdx.x;
    while (unit < TOTAL_UNITS) {
        if (unit < SPLIT_UNITS) {
            // ================= SPLIT unit =================
            int base = unit * SPLIT_CHUNK;
            int end  = base + SPLIT_CHUNK;
            if (end > TOT4) end = TOT4;
            for (int i = base + tid; i < end; i += 128) {
                const float* src;
                __nv_bfloat16 *hi, *lo;
                size_t off;
                if (i < X4) {
                    src = xin; hi = g_xhi; lo = g_xlo; off = (size_t)i * 4;
                } else {
                    int j = i - X4;
                    int w = j / W4;
                    int r = j - w * W4;
                    src = (w == 0) ? wq : (w == 1) ? wk : wv;
                    hi = g_Whi + (size_t)w * W_ELEMS;
                    lo = g_Wlo + (size_t)w * W_ELEMS;
                    off = (size_t)r * 4;
                }
                float4 v = *reinterpret_cast<const float4*>(src + off);
                float h0, l0, h1, l1, h2, l2, h3, l3;
                sp(v.x, h0, l0); sp(v.y, h1, l1); sp(v.z, h2, l2); sp(v.w, h3, l3);
                *reinterpret_cast<uint2*>(hi + off) = make_uint2(pk(h0, h1), pk(h2, h3));
                *reinterpret_cast<uint2*>(lo + off) = make_uint2(pk(l0, l1), pk(l2, l3));
            }
            __threadfence();
            __syncthreads();
            if (tid == 0) atomicAdd(&g_split, 1);

        } else if (unit < ATTN_BASE) {
            // ================= PROJ unit =================
            const int p     = unit - PROJ_BASE;
            const int h     = p / 48;
            const int r48   = p % 48;
            const int which = r48 >> 4;
            const int grp   = r48 & 15;
            const int mw = (wid & 1) * 16;
            const int nh = (wid >> 1) * 64;
            const int tok0 = grp * 512;

            // Gate: all split units published.
            if (tid == 0) {
                while (atomicAdd(&g_split, 0) < SPLIT_UNITS) __nanosleep(128);
            }
            __syncthreads();
            __threadfence();

            const __nv_bfloat16* Wh = g_Whi + (size_t)which * W_ELEMS + (size_t)h * 128 * 128;
            const __nv_bfloat16* Wl = g_Wlo + (size_t)which * W_ELEMS + (size_t)h * 128 * 128;
            __nv_bfloat16* Ohi = (which == 0) ? g_Qhi : (which == 1) ? g_Khi : g_Vhi;
            __nv_bfloat16* Olo = (which == 0) ? g_Qlo : (which == 1) ? g_Klo : g_Vlo;
            const float mul = (which == 0) ? SCALE : 1.0f;

            // Stage resident W tile (64KB) + x slice 0
#pragma unroll
            for (int it = 0; it < 16; it++) {
                int idx = tid + it * 128;
                int r = idx >> 4, s = idx & 15;
                uint32_t o = swz((uint32_t)(r * 256 + s * 16));
                size_t ge = (size_t)r * 128 + s * 8;
                cpa(sb + PWHI + o, Wh + ge);
                cpa(sb + PWLO + o, Wl + ge);
            }
            {
                size_t xoff = (size_t)tok0 * 128;
#pragma unroll
                for (int it = 0; it < 4; it++) {
                    int idx = tid + it * 128;
                    int r = idx >> 4, s = idx & 15;
                    uint32_t o = swz((uint32_t)(r * 256 + s * 16));
                    size_t ge = xoff + (size_t)r * 128 + s * 8;
                    cpa(sb + PXS0 + o, g_xhi + ge);
                    cpa(sb + PXS0 + 8192 + o, g_xlo + ge);
                }
            }
            CP_COMMIT();

            for (int s16 = 0; s16 < 16; s16++) {
                const uint32_t xb = sb + PXS0 + (s16 & 1) * PXSTR;
                const int m0 = tok0 + s16 * 32;

                CP_WAIT(0);
                __syncthreads();

                if (s16 + 1 < 16) {
                    size_t xoff = (size_t)(m0 + 32) * 128;
                    uint32_t dst = sb + PXS0 + ((s16 + 1) & 1) * PXSTR;
#pragma unroll
                    for (int it = 0; it < 4; it++) {
                        int idx = tid + it * 128;
                        int r = idx >> 4, s = idx & 15;
                        uint32_t o = swz((uint32_t)(r * 256 + s * 16));
                        size_t ge = xoff + (size_t)r * 128 + s * 8;
                        cpa(dst + o, g_xhi + ge);
                        cpa(dst + 8192 + o, g_xlo + ge);
                    }
                    CP_COMMIT();
                }

                float acc[8][4];
#pragma unroll
                for (int j = 0; j < 8; j++)
#pragma unroll
                    for (int e = 0; e < 4; e++) acc[j][e] = 0.f;

#pragma unroll
                for (int kc = 0; kc < 8; kc++) {
                    uint32_t ah[4], al[4];
                    {
                        uint32_t o = swz((uint32_t)((mw + l15) * 256 + (kc * 16 + lhi8) * 2));
                        ldsm4(xb + o, ah);
                        ldsm4(xb + 8192 + o, al);
                    }
#pragma unroll
                    for (int jj = 0; jj < 4; jj++) {
                        uint32_t bh4[4], bl4[4];
                        uint32_t o = swz((uint32_t)((nh + jj * 16 + bl_row) * 256 + (kc * 16 + bl_col) * 2));
                        ldsm4(sb + PWHI + o, bh4);
                        ldsm4(sb + PWLO + o, bl4);
                        mma16816(acc[2 * jj],     ah, bh4[0], bh4[1]);
                        mma16816(acc[2 * jj],     ah, bl4[0], bl4[1]);
                        mma16816(acc[2 * jj],     al, bh4[0], bh4[1]);
                        mma16816(acc[2 * jj + 1], ah, bh4[2], bh4[3]);
                        mma16816(acc[2 * jj + 1], ah, bl4[2], bl4[3]);
                        mma16816(acc[2 * jj + 1], al, bh4[2], bh4[3]);
                    }
                }

#pragma unroll
                for (int half = 0; half < 2; half++) {
                    int m = m0 + mw + g + half * 8;
                    int b = m >> 11;
                    int s = m & 2047;
                    size_t rbase = (((size_t)(b * Hh + h)) * Ss + s) * Dd;
#pragma unroll
                    for (int j = 0; j < 8; j++) {
                        float v0 = acc[j][half * 2]     * mul;
                        float v1 = acc[j][half * 2 + 1] * mul;
                        float h0, l0, h1, l1;
                        sp(v0, h0, l0);
                        sp(v1, h1, l1);
                        size_t off = rbase + nh + j * 8 + 2 * t;
                        *reinterpret_cast<uint32_t*>(Ohi + off) = pk(h0, h1);
                        *reinterpret_cast<uint32_t*>(Olo + off) = pk(l0, l1);
                    }
                }
                __syncthreads();
            }

            __threadfence();
            __syncthreads();
            if (tid == 0) atomicAdd(&g_done[h], 1);

        } else {
            // ================= ATTN unit =================
            const int a  = unit - ATTN_BASE;
            const int h  = a >> 7;
            const int b  = (a >> 5) & 3;
            const int qt = a & 31;
            const int bh = b * Hh + h;
            const int q0 = qt << 6;
            const int m0w = wid * 16;

            if (tid == 0) {
                while (atomicAdd(&g_done[h], 0) < 48) __nanosleep(256);
            }
            __syncthreads();
            __threadfence();

            const __nv_bfloat16* Qh = g_Qhi + ((size_t)bh * Ss + q0) * Dd;
            const __nv_bfloat16* Ql = g_Qlo + ((size_t)bh * Ss + q0) * Dd;
            const __nv_bfloat16* Kh = g_Khi + (size_t)bh * Ss * Dd;
            const __nv_bfloat16* Kl = g_Klo + (size_t)bh * Ss * Dd;
            const __nv_bfloat16* Vh = g_Vhi + (size_t)bh * Ss * Dd;
            const __nv_bfloat16* Vl = g_Vlo + (size_t)bh * Ss * Dd;

#pragma unroll
            for (int it = 0; it < 8; it++) {
                int idx = tid + it * 128;
                int r = idx >> 4, s = idx & 15;
                uint32_t o = swz((uint32_t)(r * 256 + s * 16));
                size_t ge = (size_t)r * 128 + s * 8;
                cpa(sb + QHI + o, Qh + ge);
                cpa(sb + QLO + o, Ql + ge);
            }
            prefetch_kv32(sb, 0, Kh, Kl, Vh, Vl, 0, tid);
            CP_COMMIT();

            float zacc[16][4];
#pragma unroll
            for (int j = 0; j < 16; j++)
#pragma unroll
                for (int e = 0; e < 4; e++) zacc[j][e] = 0.f;

            for (int kt = 0; kt < 64; kt++) {
                const uint32_t kb = sb + BUF0 + (kt & 1) * BUFSTRIDE;

                CP_WAIT(0);
                __syncthreads();

                if (kt + 1 < 64) {
                    prefetch_kv32(sb, (kt + 1) & 1, Kh, Kl, Vh, Vl, kt + 1, tid);
                    CP_COMMIT();
                }

                // ---- GEMM1: S[16,32] = Q . K^T ----
                float sacc[4][4];
#pragma unroll
                for (int j = 0; j < 4; j++)
#pragma unroll
                    for (int e = 0; e < 4; e++) sacc[j][e] = 0.f;

#pragma unroll
                for (int kc = 0; kc < 8; kc++) {
                    uint32_t ah[4], al[4];
                    {
                        uint32_t o = swz((uint32_t)((m0w + l15) * 256 + (kc * 16 + lhi8) * 2));
                        ldsm4(sb + QHI + o, ah);
                        ldsm4(sb + QLO + o, al);
                    }
#pragma unroll
                    for (int jj = 0; jj < 2; jj++) {
                        uint32_t bh4[4], bl4[4];
                        uint32_t o = swz((uint32_t)((jj * 16 + bl_row) * 256 + (kc * 16 + bl_col) * 2));
                        ldsm4(kb + BKHI + o, bh4);
                        ldsm4(kb + BKLO + o, bl4);
                        mma16816(sacc[2 * jj],     ah, bh4[0], bh4[1]);
                        mma16816(sacc[2 * jj],     ah, bl4[0], bl4[1]);
                        mma16816(sacc[2 * jj],     al, bh4[0], bh4[1]);
                        mma16816(sacc[2 * jj + 1], ah, bh4[2], bh4[3]);
                        mma16816(sacc[2 * jj + 1], ah, bl4[2], bl4[3]);
                        mma16816(sacc[2 * jj + 1], al, bh4[2], bh4[3]);
                    }
                }

                // ---- GEMM2: Z[16,128] += S . V ----
#pragma unroll
                for (int p = 0; p < 2; p++) {
                    uint32_t ah[4], al[4];
                    {
                        float h0, l0, h1, l1;
                        sp(sacc[2 * p][0], h0, l0); sp(sacc[2 * p][1], h1, l1);
                        ah[0] = pk(h0, h1); al[0] = pk(l0, l1);
                        sp(sacc[2 * p][2], h0, l0); sp(sacc[2 * p][3], h1, l1);
                        ah[1] = pk(h0, h1); al[1] = pk(l0, l1);
                        sp(sacc[2 * p + 1][0], h0, l0); sp(sacc[2 * p + 1][1], h1, l1);
                        ah[2] = pk(h0, h1); al[2] = pk(l0, l1);
                        sp(sacc[2 * p + 1][2], h0, l0); sp(sacc[2 * p + 1][3], h1, l1);
                        ah[3] = pk(h0, h1); al[3] = pk(l0, l1);
                    }
#pragma unroll
                    for (int np = 0; np < 8; np++) {
                        uint32_t bh4[4], bl4[4];
                        uint32_t o = swz((uint32_t)((p * 16 + l15) * 256 + (np * 16 + lhi8) * 2));
                        ldsm4t(kb + BVHI + o, bh4);
                        ldsm4t(kb + BVLO + o, bl4);
                        mma16816(zacc[2 * np],     ah, bh4[0], bh4[1]);
                        mma16816(zacc[2 * np],     ah, bl4[0], bl4[1]);
                        mma16816(zacc[2 * np],     al, bh4[0], bh4[1]);
                        mma16816(zacc[2 * np + 1], ah, bh4[2], bh4[3]);
                        mma16816(zacc[2 * np + 1], ah, bl4[2], bl4[3]);
                        mma16816(zacc[2 * np + 1], al, bh4[2], bh4[3]);
                    }
                }
            }

            // ---- epilogue: softmax over head dim ----
#pragma unroll
            for (int half = 0; half < 2; half++) {
                float e[32];
#pragma unroll
                for (int j = 0; j < 16; j++) {
                    e[2 * j]     = zacc[j][half * 2];
                    e[2 * j + 1] = zacc[j][half * 2 + 1];
                }
                float m = e[0];
#pragma unroll
                for (int c = 1; c < 32; c++) m = fmaxf(m, e[c]);
                m = fmaxf(m, __shfl_xor_sync(0xffffffffu, m, 1));
                m = fmaxf(m, __shfl_xor_sync(0xffffffffu, m, 2));

                float ssum = 0.f;
#pragma unroll
                for (int c = 0; c < 32; c++) { e[c] = __expf(e[c] - m); ssum += e[c]; }
                ssum += __shfl_xor_sync(0xffffffffu, ssum, 1);
                ssum += __shfl_xor_sync(0xffffffffu, ssum, 2);
                float inv = 1.0f / ssum;

                int row = q0 + m0w + g + half * 8;
                float* orow = out + ((size_t)bh * Ss + row) * Dd;
#pragma unroll
                for (int j = 0; j < 16; j++) {
                    float2 o2 = make_float2(e[2 * j] * inv, e[2 * j + 1] * inv);
                    *reinterpret_cast<float2*>(orow + j * 8 + 2 * t) = o2;
                }
            }
        }

        // ---- work stealing: ONE fetch per CTA, broadcast via smem ----
        if (tid == 0) *unit_sh = atomicAdd(&g_ctr, 1);
        __syncthreads();
        unit = *unit_sh;
        __syncthreads();   // smem of previous unit fully consumed before reuse
    }

    // ---- exit: last CTA resets persistent state for the next (graph) launch
    __syncthreads();
    if (tid == 0) {
        __threadfence();
        int old = atomicAdd(&g_fin, 1);
        if (old == GRID - 1) {
            g_ctr = GRID;
            g_split = 0;
#pragma unroll
            for (int i = 0; i < Hh; i++) g_done[i] = 0;
            __threadfence();
            g_fin = 0;
        }
    }
}

// ===========================================================================

extern "C" void kernel_launch(void* const* d_in, const int* in_sizes, int n_in,
                              void* d_out, int out_size)
{
    (void)in_sizes; (void)n_in; (void)out_size;
    const float* x  = (const float*)d_in[0];
    const float* Wq = (const float*)d_in[1];
    const float* Wk = (const float*)d_in[2];
    const float* Wv = (const float*)d_in[3];
    float* out = (float*)d_out;

    cudaFuncSetAttribute(fused_mma, cudaFuncAttributeMaxDynamicSharedMemorySize, FUSED_SMEM);
    fused_mma<<<GRID, 128, FUSED_SMEM>>>(out, x, Wq, Wk, Wv);
}

// round 16
// speedup vs baseline: 1.0387x; 1.0387x over previous
#include <cuda_runtime.h>
#include <cuda_bf16.h>
#include <math.h>
#include <stdint.h>

// Problem constants
#define Bq 4
#define Hh 8
#define Ss 2048
#define Dd 128
#define QKV_ELEMS (Bq*Hh*Ss*Dd)
#define X_ELEMS (Bq*Ss*Dd)       // 1,048,576
#define W_ELEMS (Hh*Dd*Dd)       // 131,072 per matrix
#define SCALE 0.0883883476483184406f   // 1/sqrt(128)

__device__ __nv_bfloat16 g_Qhi[QKV_ELEMS];
__device__ __nv_bfloat16 g_Qlo[QKV_ELEMS];
__device__ __nv_bfloat16 g_Khi[QKV_ELEMS];
__device__ __nv_bfloat16 g_Klo[QKV_ELEMS];
__device__ __nv_bfloat16 g_Vhi[QKV_ELEMS];
__device__ __nv_bfloat16 g_Vlo[QKV_ELEMS];

__device__ __nv_bfloat16 g_xhi[X_ELEMS];
__device__ __nv_bfloat16 g_xlo[X_ELEMS];
__device__ __nv_bfloat16 g_Whi[3 * W_ELEMS];
__device__ __nv_bfloat16 g_Wlo[3 * W_ELEMS];

#define ATTN_GRID 296
#define UNITS 1024
__device__ int g_ctr;

// ===========================================================================
// Common helpers
// ===========================================================================
__device__ __forceinline__ uint32_t swz(uint32_t o) {
    return o ^ (((o >> 8) & 7) << 4);
}
__device__ __forceinline__ uint32_t pk(float e_lo, float e_hi) {
    uint32_t r;
    asm("cvt.rn.bf16x2.f32 %0, %1, %2;" : "=r"(r) : "f"(e_hi), "f"(e_lo));
    return r;
}
__device__ __forceinline__ void sp(float x, float& hf, float& lf) {
    __nv_bfloat16 hb = __float2bfloat16(x);
    hf = __bfloat162float(hb);
    lf = x - hf;
}
__device__ __forceinline__ void ldsm4(uint32_t addr, uint32_t r[4]) {
    asm volatile("ldmatrix.sync.aligned.m8n8.x4.shared.b16 {%0,%1,%2,%3}, [%4];"
                 : "=r"(r[0]), "=r"(r[1]), "=r"(r[2]), "=r"(r[3]) : "r"(addr));
}
__device__ __forceinline__ void ldsm4t(uint32_t addr, uint32_t r[4]) {
    asm volatile("ldmatrix.sync.aligned.m8n8.x4.trans.shared.b16 {%0,%1,%2,%3}, [%4];"
                 : "=r"(r[0]), "=r"(r[1]), "=r"(r[2]), "=r"(r[3]) : "r"(addr));
}
__device__ __forceinline__ void mma16816(float c[4], const uint32_t a[4],
                                         uint32_t b0, uint32_t b1) {
    asm volatile(
        "mma.sync.aligned.m16n8k16.row.col.f32.bf16.bf16.f32 "
        "{%0,%1,%2,%3}, {%4,%5,%6,%7}, {%8,%9}, {%0,%1,%2,%3};"
        : "+f"(c[0]), "+f"(c[1]), "+f"(c[2]), "+f"(c[3])
        : "r"(a[0]), "r"(a[1]), "r"(a[2]), "r"(a[3]), "r"(b0), "r"(b1));
}
__device__ __forceinline__ void cpa(uint32_t dst, const void* src) {
    asm volatile("cp.async.cg.shared.global [%0], [%1], 16;" :: "r"(dst), "l"(src));
}
#define CP_COMMIT()  asm volatile("cp.async.commit_group;" ::: "memory")
#define CP_WAIT(n)   asm volatile("cp.async.wait_group %0;" :: "n"(n) : "memory")

// ===========================================================================
// Kernel 0: fused fp32 -> bf16 hi/lo split, 2 float4 per thread (MLP=2).
// ===========================================================================
#define X4 (X_ELEMS / 4)        // 262144
#define W4 (W_ELEMS / 4)        // 32768
#define TOT4 (X4 + 3 * W4)      // 360448
#define SPLIT_GRID ((TOT4 / 2 + 255) / 256)   // 704

__device__ __forceinline__ void split_one(int i, const float* __restrict__ x,
                                          const float* __restrict__ wq,
                                          const float* __restrict__ wk,
                                          const float* __restrict__ wv) {
    const float* src;
    __nv_bfloat16 *hi, *lo;
    size_t off;
    if (i < X4) {
        src = x; hi = g_xhi; lo = g_xlo; off = (size_t)i * 4;
    } else {
        int j = i - X4;
        int w = j / W4;
        int r = j - w * W4;
        src = (w == 0) ? wq : (w == 1) ? wk : wv;
        hi = g_Whi + (size_t)w * W_ELEMS;
        lo = g_Wlo + (size_t)w * W_ELEMS;
        off = (size_t)r * 4;
    }
    float4 v = *reinterpret_cast<const float4*>(src + off);
    float h0, l0, h1, l1, h2, l2, h3, l3;
    sp(v.x, h0, l0); sp(v.y, h1, l1); sp(v.z, h2, l2); sp(v.w, h3, l3);
    *reinterpret_cast<uint2*>(hi + off) = make_uint2(pk(h0, h1), pk(h2, h3));
    *reinterpret_cast<uint2*>(lo + off) = make_uint2(pk(l0, l1), pk(l2, l3));
}

__global__ __launch_bounds__(256)
void split_all(const float* __restrict__ x, const float* __restrict__ wq,
               const float* __restrict__ wk, const float* __restrict__ wv)
{
    if (blockIdx.x == 0 && threadIdx.x == 0) g_ctr = ATTN_GRID;

    int i0 = blockIdx.x * 512 + threadIdx.x;      // two interleaved halves
    if (i0 < TOT4) split_one(i0, x, wq, wk, wv);
    int i1 = i0 + 256;
    if (i1 < TOT4) split_one(i1, x, wq, wk, wv);
}

// ===========================================================================
// Kernel 1: QKV projection — W-resident, x-streamed (R13, measured best).
// grid = (Hh, 16, 3), block = 128 (4 warps), smem 96KB.
// ===========================================================================
#define PWHI 0
#define PWLO 32768
#define PXS0 65536
#define PXSTR 16384
#define PROJ_SMEM 98304

__global__ __launch_bounds__(128, 2)
void proj_mma()
{
    extern __shared__ char sm[];
    const uint32_t sb = (uint32_t)__cvta_generic_to_shared(sm);
    const int tid  = threadIdx.x;
    const int wid  = tid >> 5;
    const int lane = tid & 31;
    const int h     = blockIdx.x;
    const int grp   = blockIdx.y;
    const int which = blockIdx.z;
    const int mw = (wid & 1) * 16;
    const int nh = (wid >> 1) * 64;

    const __nv_bfloat16* Wh = g_Whi + (size_t)which * W_ELEMS + (size_t)h * 128 * 128;
    const __nv_bfloat16* Wl = g_Wlo + (size_t)which * W_ELEMS + (size_t)h * 128 * 128;
    __nv_bfloat16* Ohi = (which == 0) ? g_Qhi : (which == 1) ? g_Khi : g_Vhi;
    __nv_bfloat16* Olo = (which == 0) ? g_Qlo : (which == 1) ? g_Klo : g_Vlo;

    const int tok0 = grp * 512;

#pragma unroll
    for (int it = 0; it < 16; it++) {
        int idx = tid + it * 128;
        int r = idx >> 4, s = idx & 15;
        uint32_t o = swz((uint32_t)(r * 256 + s * 16));
        size_t ge = (size_t)r * 128 + s * 8;
        cpa(sb + PWHI + o, Wh + ge);
        cpa(sb + PWLO + o, Wl + ge);
    }
    {
        size_t xoff = (size_t)tok0 * 128;
#pragma unroll
        for (int it = 0; it < 4; it++) {
            int idx = tid + it * 128;
            int r = idx >> 4, s = idx & 15;
            uint32_t o = swz((uint32_t)(r * 256 + s * 16));
            size_t ge = xoff + (size_t)r * 128 + s * 8;
            cpa(sb + PXS0 + o, g_xhi + ge);
            cpa(sb + PXS0 + 8192 + o, g_xlo + ge);
        }
    }
    CP_COMMIT();

    const int l15 = lane & 15;
    const int lhi8 = (lane >> 4) << 3;
    const int bl_row = ((lane >> 4) << 3) + (lane & 7);
    const int bl_col = ((lane >> 3) & 1) << 3;
    const float mul = (which == 0) ? SCALE : 1.0f;
    const int g = lane >> 2;
    const int t = lane & 3;

    for (int s16 = 0; s16 < 16; s16++) {
        const uint32_t xb = sb + PXS0 + (s16 & 1) * PXSTR;
        const int m0 = tok0 + s16 * 32;

        CP_WAIT(0);
        __syncthreads();

        if (s16 + 1 < 16) {
            size_t xoff = (size_t)(m0 + 32) * 128;
            uint32_t dst = sb + PXS0 + ((s16 + 1) & 1) * PXSTR;
#pragma unroll
            for (int it = 0; it < 4; it++) {
                int idx = tid + it * 128;
                int r = idx >> 4, s = idx & 15;
                uint32_t o = swz((uint32_t)(r * 256 + s * 16));
                size_t ge = xoff + (size_t)r * 128 + s * 8;
                cpa(dst + o, g_xhi + ge);
                cpa(dst + 8192 + o, g_xlo + ge);
            }
            CP_COMMIT();
        }

        float acc[8][4];
#pragma unroll
        for (int j = 0; j < 8; j++)
#pragma unroll
            for (int e = 0; e < 4; e++) acc[j][e] = 0.f;

#pragma unroll
        for (int kc = 0; kc < 8; kc++) {
            uint32_t ah[4], al[4];
            {
                uint32_t o = swz((uint32_t)((mw + l15) * 256 + (kc * 16 + lhi8) * 2));
                ldsm4(xb + o, ah);
                ldsm4(xb + 8192 + o, al);
            }
#pragma unroll
            for (int jj = 0; jj < 4; jj++) {
                uint32_t bh4[4], bl4[4];
                uint32_t o = swz((uint32_t)((nh + jj * 16 + bl_row) * 256 + (kc * 16 + bl_col) * 2));
                ldsm4(sb + PWHI + o, bh4);
                ldsm4(sb + PWLO + o, bl4);
                mma16816(acc[2 * jj],     ah, bh4[0], bh4[1]);
                mma16816(acc[2 * jj],     ah, bl4[0], bl4[1]);
                mma16816(acc[2 * jj],     al, bh4[0], bh4[1]);
                mma16816(acc[2 * jj + 1], ah, bh4[2], bh4[3]);
                mma16816(acc[2 * jj + 1], ah, bl4[2], bl4[3]);
                mma16816(acc[2 * jj + 1], al, bh4[2], bh4[3]);
            }
        }

#pragma unroll
        for (int half = 0; half < 2; half++) {
            int m = m0 + mw + g + half * 8;
            int b = m >> 11;
            int s = m & 2047;
            size_t rbase = (((size_t)(b * Hh + h)) * Ss + s) * Dd;
#pragma unroll
            for (int j = 0; j < 8; j++) {
                float v0 = acc[j][half * 2]     * mul;
                float v1 = acc[j][half * 2 + 1] * mul;
                float h0, l0, h1, l1;
                sp(v0, h0, l0);
                sp(v1, h1, l1);
                size_t off = rbase + nh + j * 8 + 2 * t;
                *reinterpret_cast<uint32_t*>(Ohi + off) = pk(h0, h1);
                *reinterpret_cast<uint32_t*>(Olo + off) = pk(l0, l1);
            }
        }
        __syncthreads();
    }
}

// ===========================================================================
// Kernel 2: persistent tensor-core attention (R8 structure, measured 423us)
// + R16: work-steal fetched BEFORE the epilogue to hide ATOMG latency.
// ===========================================================================
#define QHI 0
#define QLO 16384
#define BUF0 32768
#define BUFSTRIDE 32768
#define BKHI 0
#define BKLO 8192
#define BVHI 16384
#define BVLO 24576
#define UNIT_SLOT 98304
#define ATTN_SMEM 98432

__device__ __forceinline__ void prefetch_kv32(uint32_t sb, int buf,
                                              const __nv_bfloat16* Kh, const __nv_bfloat16* Kl,
                                              const __nv_bfloat16* Vh, const __nv_bfloat16* Vl,
                                              int kt, int tid) {
    uint32_t base = sb + BUF0 + buf * BUFSTRIDE;
    size_t goff = (size_t)kt * 32 * 128;
#pragma unroll
    for (int it = 0; it < 4; it++) {
        int idx = tid + it * 128;
        int r = idx >> 4, s = idx & 15;
        uint32_t o = swz((uint32_t)(r * 256 + s * 16));
        size_t ge = goff + (size_t)r * 128 + s * 8;
        cpa(base + BKHI + o, Kh + ge);
        cpa(base + BKLO + o, Kl + ge);
        cpa(base + BVHI + o, Vh + ge);
        cpa(base + BVLO + o, Vl + ge);
    }
}

__global__ __launch_bounds__(128, 2)
void attn_mma(float* __restrict__ out)
{
    extern __shared__ char sm[];
    const uint32_t sb = (uint32_t)__cvta_generic_to_shared(sm);
    volatile int* unit_sh = reinterpret_cast<volatile int*>(sm + UNIT_SLOT);
    const int tid  = threadIdx.x;
    const int wid  = tid >> 5;
    const int lane = tid & 31;
    const int m0w = wid * 16;

    const int l15 = lane & 15;
    const int lhi8 = (lane >> 4) << 3;
    const int bl_row = ((lane >> 4) << 3) + (lane & 7);
    const int bl_col = ((lane >> 3) & 1) << 3;
    const int g = lane >> 2;
    const int t = lane & 3;

    int unit = blockIdx.x;
    while (unit < UNITS) {
        const int bh = unit >> 5;
        const int q0 = (unit & 31) << 6;

        const __nv_bfloat16* Qh = g_Qhi + ((size_t)bh * Ss + q0) * Dd;
        const __nv_bfloat16* Ql = g_Qlo + ((size_t)bh * Ss + q0) * Dd;
        const __nv_bfloat16* Kh = g_Khi + (size_t)bh * Ss * Dd;
        const __nv_bfloat16* Kl = g_Klo + (size_t)bh * Ss * Dd;
        const __nv_bfloat16* Vh = g_Vhi + (size_t)bh * Ss * Dd;
        const __nv_bfloat16* Vl = g_Vlo + (size_t)bh * Ss * Dd;

        // Stage Q (64 x 128 hi/lo) + prefetch KV tile 0 (one group)
#pragma unroll
        for (int it = 0; it < 8; it++) {
            int idx = tid + it * 128;
            int r = idx >> 4, s = idx & 15;
            uint32_t o = swz((uint32_t)(r * 256 + s * 16));
            size_t ge = (size_t)r * 128 + s * 8;
            cpa(sb + QHI + o, Qh + ge);
            cpa(sb + QLO + o, Ql + ge);
        }
        prefetch_kv32(sb, 0, Kh, Kl, Vh, Vl, 0, tid);
        CP_COMMIT();

        float zacc[16][4];
#pragma unroll
        for (int j = 0; j < 16; j++)
#pragma unroll
            for (int e = 0; e < 4; e++) zacc[j][e] = 0.f;

        for (int kt = 0; kt < 64; kt++) {
            const uint32_t kb = sb + BUF0 + (kt & 1) * BUFSTRIDE;

            CP_WAIT(0);
            __syncthreads();

            if (kt + 1 < 64) {
                prefetch_kv32(sb, (kt + 1) & 1, Kh, Kl, Vh, Vl, kt + 1, tid);
                CP_COMMIT();
            }

            // ---- GEMM1: S[16,32] = Q . K^T ----
            float sacc[4][4];
#pragma unroll
            for (int j = 0; j < 4; j++)
#pragma unroll
                for (int e = 0; e < 4; e++) sacc[j][e] = 0.f;

#pragma unroll
            for (int kc = 0; kc < 8; kc++) {
                uint32_t ah[4], al[4];
                {
                    uint32_t o = swz((uint32_t)((m0w + l15) * 256 + (kc * 16 + lhi8) * 2));
                    ldsm4(sb + QHI + o, ah);
                    ldsm4(sb + QLO + o, al);
                }
#pragma unroll
                for (int jj = 0; jj < 2; jj++) {
                    uint32_t bh4[4], bl4[4];
                    uint32_t o = swz((uint32_t)((jj * 16 + bl_row) * 256 + (kc * 16 + bl_col) * 2));
                    ldsm4(kb + BKHI + o, bh4);
                    ldsm4(kb + BKLO + o, bl4);
                    mma16816(sacc[2 * jj],     ah, bh4[0], bh4[1]);
                    mma16816(sacc[2 * jj],     ah, bl4[0], bl4[1]);
                    mma16816(sacc[2 * jj],     al, bh4[0], bh4[1]);
                    mma16816(sacc[2 * jj + 1], ah, bh4[2], bh4[3]);
                    mma16816(sacc[2 * jj + 1], ah, bl4[2], bl4[3]);
                    mma16816(sacc[2 * jj + 1], al, bh4[2], bh4[3]);
                }
            }

            // ---- GEMM2: Z[16,128] += S . V ----
#pragma unroll
            for (int p = 0; p < 2; p++) {
                uint32_t ah[4], al[4];
                {
                    float h0, l0, h1, l1;
                    sp(sacc[2 * p][0], h0, l0); sp(sacc[2 * p][1], h1, l1);
                    ah[0] = pk(h0, h1); al[0] = pk(l0, l1);
                    sp(sacc[2 * p][2], h0, l0); sp(sacc[2 * p][3], h1, l1);
                    ah[1] = pk(h0, h1); al[1] = pk(l0, l1);
                    sp(sacc[2 * p + 1][0], h0, l0); sp(sacc[2 * p + 1][1], h1, l1);
                    ah[2] = pk(h0, h1); al[2] = pk(l0, l1);
                    sp(sacc[2 * p + 1][2], h0, l0); sp(sacc[2 * p + 1][3], h1, l1);
                    ah[3] = pk(h0, h1); al[3] = pk(l0, l1);
                }
#pragma unroll
                for (int np = 0; np < 8; np++) {
                    uint32_t bh4[4], bl4[4];
                    uint32_t o = swz((uint32_t)((p * 16 + l15) * 256 + (np * 16 + lhi8) * 2));
                    ldsm4t(kb + BVHI + o, bh4);
                    ldsm4t(kb + BVLO + o, bl4);
                    mma16816(zacc[2 * np],     ah, bh4[0], bh4[1]);
                    mma16816(zacc[2 * np],     ah, bl4[0], bl4[1]);
                    mma16816(zacc[2 * np],     al, bh4[0], bh4[1]);
                    mma16816(zacc[2 * np + 1], ah, bh4[2], bh4[3]);
                    mma16816(zacc[2 * np + 1], ah, bl4[2], bl4[3]);
                    mma16816(zacc[2 * np + 1], al, bh4[2], bh4[3]);
                }
            }
        }

        // ---- fetch NEXT unit now; its latency hides under the epilogue ----
        if (tid == 0) *unit_sh = atomicAdd(&g_ctr, 1);

        // ---- epilogue: softmax over head dim (registers + gmem only) ----
#pragma unroll
        for (int half = 0; half < 2; half++) {
            float e[32];
#pragma unroll
            for (int j = 0; j < 16; j++) {
                e[2 * j]     = zacc[j][half * 2];
                e[2 * j + 1] = zacc[j][half * 2 + 1];
            }
            float m = e[0];
#pragma unroll
            for (int c = 1; c < 32; c++) m = fmaxf(m, e[c]);
            m = fmaxf(m, __shfl_xor_sync(0xffffffffu, m, 1));
            m = fmaxf(m, __shfl_xor_sync(0xffffffffu, m, 2));

            float ssum = 0.f;
#pragma unroll
            for (int c = 0; c < 32; c++) { e[c] = __expf(e[c] - m); ssum += e[c]; }
            ssum += __shfl_xor_sync(0xffffffffu, ssum, 1);
            ssum += __shfl_xor_sync(0xffffffffu, ssum, 2);
            float inv = 1.0f / ssum;

            int row = q0 + m0w + g + half * 8;
            float* orow = out + ((size_t)bh * Ss + row) * Dd;
#pragma unroll
            for (int j = 0; j < 16; j++) {
                float2 o2 = make_float2(e[2 * j] * inv, e[2 * j + 1] * inv);
                *reinterpret_cast<float2*>(orow + j * 8 + 2 * t) = o2;
            }
        }

        __syncthreads();          // unit_sh visible; smem free for next unit
        unit = *unit_sh;
    }
}

// ===========================================================================

extern "C" void kernel_launch(void* const* d_in, const int* in_sizes, int n_in,
                              void* d_out, int out_size)
{
    (void)in_sizes; (void)n_in; (void)out_size;
    const float* x  = (const float*)d_in[0];
    const float* Wq = (const float*)d_in[1];
    const float* Wk = (const float*)d_in[2];
    const float* Wv = (const float*)d_in[3];
    float* out = (float*)d_out;

    cudaFuncSetAttribute(proj_mma, cudaFuncAttributeMaxDynamicSharedMemorySize, PROJ_SMEM);
    cudaFuncSetAttribute(attn_mma, cudaFuncAttributeMaxDynamicSharedMemorySize, ATTN_SMEM);

    split_all<<<SPLIT_GRID, 256>>>(x, Wq, Wk, Wv);
    proj_mma<<<dim3(Hh, 16, 3), 128, PROJ_SMEM>>>();
    attn_mma<<<ATTN_GRID, 128, ATTN_SMEM>>>(out);
}